// round 1
// baseline (speedup 1.0000x reference)
#include <cuda_runtime.h>
#include <cuda_bf16.h>
#include <cstdint>

#define N_NODES_MAX 50000
#define FDIM 128
#define F4 (FDIM / 4)

// Scratch (device globals — no allocation allowed in kernel_launch)
__device__ float g_h[N_NODES_MAX * FDIM];   // h = x @ W
__device__ float g_dis[N_NODES_MAX];        // deg^{-1/2}
__device__ int   g_is32;                    // 1 if edge_index is int32, 0 if int64

// ---------------------------------------------------------------------------
// Detect edge_index dtype. True int64 indices are all < N_NODES; int32 data
// reinterpreted as u64 packs two indices per word -> almost surely >= 2^32.
__global__ void k_detect(const unsigned long long* __restrict__ e) {
    if (blockIdx.x == 0 && threadIdx.x == 0) {
        int f = 0;
        #pragma unroll 4
        for (int i = 0; i < 256; i++) {
            if (e[i] >= (unsigned long long)N_NODES_MAX) { f = 1; break; }
        }
        g_is32 = f;
    }
}

__device__ __forceinline__ int load_idx(const void* __restrict__ e, long long pos) {
    if (g_is32) return ((const int*)e)[pos];
    return (int)(((const long long*)e)[pos]);
}

// ---------------------------------------------------------------------------
// deg[i] starts at 1.0 (self loop)
__global__ void k_initdeg(int n) {
    int i = blockIdx.x * blockDim.x + threadIdx.x;
    if (i < n) g_dis[i] = 1.0f;
}

// count in-degree over edges (target = col = edge_index[1])
__global__ void k_count(const void* __restrict__ e, int ne) {
    int i = blockIdx.x * blockDim.x + threadIdx.x;
    if (i < ne) {
        int col = load_idx(e, (long long)ne + i);
        atomicAdd(&g_dis[col], 1.0f);
    }
}

// dis = deg^{-1/2}  (deg >= 1 always, self loop)
__global__ void k_rsqrt(int n) {
    int i = blockIdx.x * blockDim.x + threadIdx.x;
    if (i < n) g_dis[i] = rsqrtf(g_dis[i]);
}

// ---------------------------------------------------------------------------
// GEMM: g_h = x @ W.  128 threads = 128 output columns; 8 rows per block.
// x-tile in smem (broadcast reads), W streamed through L1 (64KB, resident).
#define ROWS_PB 8
__global__ void __launch_bounds__(FDIM) k_gemm(const float* __restrict__ x,
                                               const float* __restrict__ W,
                                               int n) {
    __shared__ float xs[ROWS_PB][FDIM];
    const int t  = threadIdx.x;           // output column
    const int r0 = blockIdx.x * ROWS_PB;

    #pragma unroll
    for (int r = 0; r < ROWS_PB; r++) {
        int row = r0 + r;
        xs[r][t] = (row < n) ? x[(size_t)row * FDIM + t] : 0.0f;
    }
    __syncthreads();

    float acc[ROWS_PB];
    #pragma unroll
    for (int r = 0; r < ROWS_PB; r++) acc[r] = 0.0f;

    #pragma unroll 4
    for (int k = 0; k < FDIM; k++) {
        float w = __ldg(&W[(size_t)k * FDIM + t]);   // coalesced, L1-resident
        #pragma unroll
        for (int r = 0; r < ROWS_PB; r++) acc[r] += xs[r][k] * w;
    }

    #pragma unroll
    for (int r = 0; r < ROWS_PB; r++) {
        int row = r0 + r;
        if (row < n) g_h[(size_t)row * FDIM + t] = acc[r];
    }
}

// ---------------------------------------------------------------------------
// out[i] = h[i] * dis[i]^2 + b   (self-loop term; also initializes poisoned out)
__global__ void k_selfinit(const float* __restrict__ b, float* __restrict__ out, int n) {
    int idx = blockIdx.x * blockDim.x + threadIdx.x;   // over n * F4 float4s
    int total = n * F4;
    if (idx >= total) return;
    int node = idx / F4;
    int c4   = idx - node * F4;
    float d = g_dis[node];
    float s = d * d;
    float4 h4 = ((const float4*)g_h)[idx];
    float4 b4 = ((const float4*)b)[c4];
    float4 o;
    o.x = h4.x * s + b4.x;
    o.y = h4.y * s + b4.y;
    o.z = h4.z * s + b4.z;
    o.w = h4.w * s + b4.w;
    ((float4*)out)[idx] = o;
}

// ---------------------------------------------------------------------------
// Edge scatter: one warp per edge. Lane l handles float4 chunk l (32*4 = 128).
// h and out are both L2-resident (25.6MB each); vector atomics (sm_90+).
__global__ void __launch_bounds__(256) k_scatter(const void* __restrict__ e,
                                                 float* __restrict__ out,
                                                 int ne) {
    int warp = (int)((blockIdx.x * (long long)blockDim.x + threadIdx.x) >> 5);
    int lane = threadIdx.x & 31;
    if (warp >= ne) return;

    int row = load_idx(e, warp);                  // source
    int col = load_idx(e, (long long)ne + warp);  // target
    float norm = g_dis[row] * g_dis[col];

    float4 v = ((const float4*)(g_h + (size_t)row * FDIM))[lane];
    v.x *= norm; v.y *= norm; v.z *= norm; v.w *= norm;

    atomicAdd(((float4*)(out + (size_t)col * FDIM)) + lane, v);
}

// ---------------------------------------------------------------------------
extern "C" void kernel_launch(void* const* d_in, const int* in_sizes, int n_in,
                              void* d_out, int out_size) {
    const float* x  = (const float*)d_in[0];
    const void*  ei = d_in[1];                 // int64 or int32, detected on device
    const float* W  = (const float*)d_in[2];
    const float* b  = (const float*)d_in[3];
    float* out = (float*)d_out;

    const int n  = in_sizes[0] / FDIM;         // 50000
    const int ne = in_sizes[1] / 2;            // 500000 (element count / 2)

    k_detect<<<1, 32>>>((const unsigned long long*)ei);
    k_initdeg<<<(n + 255) / 256, 256>>>(n);
    k_count<<<(ne + 255) / 256, 256>>>(ei, ne);
    k_rsqrt<<<(n + 255) / 256, 256>>>(n);
    k_gemm<<<(n + ROWS_PB - 1) / ROWS_PB, FDIM>>>(x, W, n);
    k_selfinit<<<(n * F4 + 255) / 256, 256>>>(b, out, n);
    // one warp per edge: 8 edges per 256-thread block
    k_scatter<<<(ne + 7) / 8, 256>>>(ei, out, ne);
}

// round 2
// speedup vs baseline: 1.2500x; 1.2500x over previous
#include <cuda_runtime.h>
#include <cuda_bf16.h>
#include <cstdint>

#define N_NODES_MAX 50000
#define N_EDGES_MAX 500000
#define FDIM 128
#define F4 (FDIM / 4)
#define SCAN_B 256
#define NBLK_SCAN ((N_NODES_MAX + SCAN_B - 1) / SCAN_B)   // 196

// Scratch (device globals — no allocation allowed)
__device__ float g_h[N_NODES_MAX * FDIM];    // h = x @ W
__device__ float g_dis[N_NODES_MAX];         // deg^{-1/2}
__device__ int   g_cnt[N_NODES_MAX];         // in-degree (edges only)
__device__ int   g_woff[N_NODES_MAX];        // working offsets (bucket fill -> end ptr)
__device__ int   g_off[N_NODES_MAX];         // block-local exclusive scan
__device__ int   g_bsum[NBLK_SCAN];          // per-block sums
__device__ int   g_boff[NBLK_SCAN];          // scanned block sums
__device__ int   g_ebuf[N_EDGES_MAX];        // CSR: source row per (sorted-by-col) edge
__device__ int   g_is32;

// ---------------------------------------------------------------------------
// setup: zero counters; thread (0,0) detects edge dtype.
// int64 indices are all < N_NODES; int32 data read as u64 -> >= 2^32 w.h.p.
__global__ void k_setup(const unsigned long long* __restrict__ e, int n) {
    int i = blockIdx.x * blockDim.x + threadIdx.x;
    if (i < n) g_cnt[i] = 0;
    if (i == 0) {
        int f = 0;
        for (int j = 0; j < 256; j++)
            if (e[j] >= (unsigned long long)N_NODES_MAX) { f = 1; break; }
        g_is32 = f;
    }
}

__device__ __forceinline__ int load_idx(const void* __restrict__ e, long long pos) {
    if (g_is32) return ((const int*)e)[pos];
    return (int)(((const long long*)e)[pos]);
}

// count in-degree over edges (target = col = edge_index[1])
__global__ void k_count(const void* __restrict__ e, int ne) {
    int i = blockIdx.x * blockDim.x + threadIdx.x;
    if (i < ne) atomicAdd(&g_cnt[load_idx(e, (long long)ne + i)], 1);
}

// block-level exclusive scan of g_cnt; also dis = rsqrt(deg+1)
__global__ void __launch_bounds__(SCAN_B) k_scan1(int n) {
    __shared__ int sh[SCAN_B];
    int t = threadIdx.x;
    int i = blockIdx.x * SCAN_B + t;
    int c = (i < n) ? g_cnt[i] : 0;
    if (i < n) g_dis[i] = rsqrtf((float)(c + 1));
    sh[t] = c;
    #pragma unroll
    for (int off = 1; off < SCAN_B; off <<= 1) {
        __syncthreads();
        int v = (t >= off) ? sh[t - off] : 0;
        __syncthreads();
        sh[t] += v;
    }
    __syncthreads();
    if (i < n) g_off[i] = sh[t] - c;                  // exclusive
    if (t == SCAN_B - 1) g_bsum[blockIdx.x] = sh[t];  // block total
}

// scan the 196 block sums (single block)
__global__ void __launch_bounds__(SCAN_B) k_scan2(int nb) {
    __shared__ int sh[SCAN_B];
    int t = threadIdx.x;
    int c = (t < nb) ? g_bsum[t] : 0;
    sh[t] = c;
    #pragma unroll
    for (int off = 1; off < SCAN_B; off <<= 1) {
        __syncthreads();
        int v = (t >= off) ? sh[t - off] : 0;
        __syncthreads();
        sh[t] += v;
    }
    __syncthreads();
    if (t < nb) g_boff[t] = sh[t] - c;
}

// finalize global offsets
__global__ void k_scan3(int n) {
    int i = blockIdx.x * blockDim.x + threadIdx.x;
    if (i < n) g_woff[i] = g_off[i] + g_boff[i >> 8];
}

// bucket fill: place source row of each edge into its target's segment
__global__ void k_bucket(const void* __restrict__ e, int ne) {
    int i = blockIdx.x * blockDim.x + threadIdx.x;
    if (i < ne) {
        int row = load_idx(e, i);
        int col = load_idx(e, (long long)ne + i);
        int pos = atomicAdd(&g_woff[col], 1);
        g_ebuf[pos] = row;
    }
}

// ---------------------------------------------------------------------------
// GEMM: g_h = x @ W.  128 threads = 128 output columns; 16 rows per block.
#define ROWS_PB 16
__global__ void __launch_bounds__(FDIM) k_gemm(const float* __restrict__ x,
                                               const float* __restrict__ W,
                                               int n) {
    __shared__ float xs[ROWS_PB][FDIM];
    const int t  = threadIdx.x;
    const int r0 = blockIdx.x * ROWS_PB;

    #pragma unroll
    for (int r = 0; r < ROWS_PB; r++) {
        int row = r0 + r;
        xs[r][t] = (row < n) ? x[(size_t)row * FDIM + t] : 0.0f;
    }
    __syncthreads();

    float acc[ROWS_PB];
    #pragma unroll
    for (int r = 0; r < ROWS_PB; r++) acc[r] = 0.0f;

    #pragma unroll 4
    for (int k = 0; k < FDIM; k++) {
        float w = __ldg(&W[(size_t)k * FDIM + t]);
        #pragma unroll
        for (int r = 0; r < ROWS_PB; r++) acc[r] += xs[r][k] * w;
    }

    #pragma unroll
    for (int r = 0; r < ROWS_PB; r++) {
        int row = r0 + r;
        if (row < n) g_h[(size_t)row * FDIM + t] = acc[r];
    }
}

// ---------------------------------------------------------------------------
// Aggregate: one warp per target node. lane l owns float4 chunk l.
// out[i] = b + dis[i]^2 * h[i] + sum_j dis[i]*dis[row_j] * h[row_j]
__global__ void __launch_bounds__(256) k_aggregate(const float* __restrict__ b,
                                                   float* __restrict__ out,
                                                   int n) {
    int node = (int)((blockIdx.x * (long long)blockDim.x + threadIdx.x) >> 5);
    int lane = threadIdx.x & 31;
    if (node >= n) return;

    float s   = g_dis[node];
    int   end = g_woff[node];            // after bucket fill: start + cnt
    int   cnt = g_cnt[node];
    int   j   = end - cnt;

    const float4* __restrict__ h4 = (const float4*)g_h;

    float4 acc = ((const float4*)b)[lane];
    {
        float ss = s * s;
        float4 hv = h4[(size_t)node * 32 + lane];
        acc.x += ss * hv.x; acc.y += ss * hv.y;
        acc.z += ss * hv.z; acc.w += ss * hv.w;
    }

    // 2-edge unroll for MLP on the 16B gathers
    for (; j + 1 < end; j += 2) {
        int r0 = g_ebuf[j];
        int r1 = g_ebuf[j + 1];
        float n0 = s * g_dis[r0];
        float n1 = s * g_dis[r1];
        float4 v0 = h4[(size_t)r0 * 32 + lane];
        float4 v1 = h4[(size_t)r1 * 32 + lane];
        acc.x += n0 * v0.x + n1 * v1.x;
        acc.y += n0 * v0.y + n1 * v1.y;
        acc.z += n0 * v0.z + n1 * v1.z;
        acc.w += n0 * v0.w + n1 * v1.w;
    }
    if (j < end) {
        int r0 = g_ebuf[j];
        float n0 = s * g_dis[r0];
        float4 v0 = h4[(size_t)r0 * 32 + lane];
        acc.x += n0 * v0.x; acc.y += n0 * v0.y;
        acc.z += n0 * v0.z; acc.w += n0 * v0.w;
    }

    ((float4*)out)[(size_t)node * 32 + lane] = acc;
}

// ---------------------------------------------------------------------------
extern "C" void kernel_launch(void* const* d_in, const int* in_sizes, int n_in,
                              void* d_out, int out_size) {
    const float* x  = (const float*)d_in[0];
    const void*  ei = d_in[1];
    const float* W  = (const float*)d_in[2];
    const float* b  = (const float*)d_in[3];
    float* out = (float*)d_out;

    const int n  = in_sizes[0] / FDIM;   // 50000
    const int ne = in_sizes[1] / 2;      // 500000
    const int nb = (n + SCAN_B - 1) / SCAN_B;

    k_setup <<<(n + 255) / 256, 256>>>((const unsigned long long*)ei, n);
    k_count <<<(ne + 255) / 256, 256>>>(ei, ne);
    k_scan1 <<<nb, SCAN_B>>>(n);
    k_scan2 <<<1, SCAN_B>>>(nb);
    k_scan3 <<<(n + 255) / 256, 256>>>(n);
    k_bucket<<<(ne + 255) / 256, 256>>>(ei, ne);
    k_gemm  <<<(n + ROWS_PB - 1) / ROWS_PB, FDIM>>>(x, W, n);
    k_aggregate<<<(n * 32 + 255) / 256, 256>>>(b, out, n);
}